// round 15
// baseline (speedup 1.0000x reference)
#include <cuda_runtime.h>
#include <cstdint>

// BaseEncoder: out[b, f, c] = (bitcast<u32>(x[b,f]) >> (31 - c)) & 1  (float).
// c==0 is bit 31 (sign == (x<0) channel); c>=1 are bits 30..0 of |x|.
//
// FINAL (R8 configuration, frozen; reproduced at 45.216 us in R8 and R13).
//
// Floor analysis (R8-R13): ~277 MB crosses the SM<->L2 interface in
// ~41.8 us = 6.6 TB/s ~= 96% of the measured path-independent B300 LTS
// chip cap (~6300 B/cyc in the fixed L2 clock domain ~= 6.9 TB/s).
// Disproven alternatives: .cs streaming stores (-3%), st.global.v8 (-3%),
// persistent grid (-8%), THREADS=128 (neutral). TMA stores are predicted
// neutral by direct HW measurement (TMA == LDG.cv at the LTS cap).
// Output bytes (256 MiB fp32) are irreducible; input is 3% of traffic.
//
// Structure: each block owns a contiguous chunk of THREADS*ITERS float4s.
// Each thread front-batches ITERS independent LDGs (MLP=8; 8 lanes share
// one input word via broadcast), then computes + stores ITERS float4s.
// Each warp store instruction writes 512 contiguous bytes (perfectly
// coalesced STG.128). The bit-channel offset (t & 7) is loop-invariant
// because THREADS % 8 == 0, so the per-word pre-shift hoists.

constexpr int ITERS   = 8;
constexpr int THREADS = 256;
constexpr int CHUNK   = THREADS * ITERS;   // float4s per block = 2048
constexpr int WSTRIDE = THREADS / 8;       // input words per iteration step

__global__ void __launch_bounds__(THREADS)
base_encoder_kernel(const uint32_t* __restrict__ x,
                    float4* __restrict__ out,
                    int n4)
{
    const uint32_t ONE = 0x3f800000u;      // bit pattern of 1.0f

    int t0 = blockIdx.x * CHUNK + threadIdx.x;
    int w0 = t0 >> 3;                      // input word index for iteration 0
    int c0 = (t0 & 7) * 4;                 // loop-invariant bit-channel offset

    if (t0 + (ITERS - 1) * THREADS < n4) {
        // Fast path: all ITERS iterations in bounds. Front-batch the loads.
        uint32_t u[ITERS];
        #pragma unroll
        for (int i = 0; i < ITERS; i++)
            u[i] = __ldg(&x[w0 + i * WSTRIDE]);   // 8 lanes share one word

        #pragma unroll
        for (int i = 0; i < ITERS; i++) {
            uint32_t base = u[i] << c0;    // bit 31 of base == channel c0
            float4 v;
            v.x = __uint_as_float( (base >> 31)       * ONE);
            v.y = __uint_as_float(((base >> 30) & 1u) * ONE);
            v.z = __uint_as_float(((base >> 29) & 1u) * ONE);
            v.w = __uint_as_float(((base >> 28) & 1u) * ONE);
            out[t0 + i * THREADS] = v;
        }
    } else {
        // Tail path (unused for the fixed 4096x512x32 shape, kept for safety).
        #pragma unroll
        for (int i = 0; i < ITERS; i++) {
            int t = t0 + i * THREADS;
            if (t < n4) {
                uint32_t base = __ldg(&x[t >> 3]) << c0;
                float4 v;
                v.x = __uint_as_float( (base >> 31)       * ONE);
                v.y = __uint_as_float(((base >> 30) & 1u) * ONE);
                v.z = __uint_as_float(((base >> 29) & 1u) * ONE);
                v.w = __uint_as_float(((base >> 28) & 1u) * ONE);
                out[t] = v;
            }
        }
    }
}

extern "C" void kernel_launch(void* const* d_in, const int* in_sizes, int n_in,
                              void* d_out, int out_size)
{
    const uint32_t* x = (const uint32_t*)d_in[0];
    float4* out = (float4*)d_out;

    int n4 = out_size / 4;                 // 4096*512*32/4 = 16,777,216
    int blocks = (n4 + CHUNK - 1) / CHUNK; // 8192 for the fixed shape

    base_encoder_kernel<<<blocks, THREADS>>>(x, out, n4);
}